// round 10
// baseline (speedup 1.0000x reference)
#include <cuda_runtime.h>
#include <cuda_fp16.h>
#include <cstdint>

#define N_NODES 50000
#define N_PAD   50048      // 391 * 128
#define N_EDGES 800000
#define D_FEAT  128
#define UNITS   256
#define ELLW    80         // padded ELL width (max degree ~35 whp)

#define FILL_BLOCKS 3125   // N_EDGES / 256
#define CONV_BLOCKS 6250   // N_NODES * D_FEAT / 4 / 256
#define CW_BLOCKS   128    // D_FEAT
#define MEGA_BLOCKS (FILL_BLOCKS + CONV_BLOCKS + CW_BLOCKS)

// ---------------------------------------------------------------- scratch ---
__device__ unsigned long long g_pack[N_NODES];  // count<<42 | fix24(val sum)
__device__ float  g_invd[N_NODES];
__device__ int2   g_ell[(size_t)N_NODES * ELLW];   // {col, val-bits}
__device__ __half g_feath[(size_t)N_NODES * D_FEAT];  // raw fp16 features
// fp16 GEMM operands (zero-init; pad rows never written -> stay zero)
__device__ __half g_Ah[(size_t)N_PAD * D_FEAT];
__device__ __half g_Wh[(size_t)UNITS * D_FEAT];    // transposed: [n][k]

// -------------------------------------------------------------------- zero --
__global__ void zero_kernel() {
    int i = blockIdx.x * blockDim.x + threadIdx.x;
    if (i < N_NODES) g_pack[i] = 0ull;
}

__device__ __forceinline__ float pack_to_inv(unsigned long long p) {
    float deg = (float)(p & ((1ull << 42) - 1)) * (1.0f / 16777216.0f);
    return rsqrtf(deg + 1.0f);
}

// ------------------- mega: ELL fill  ||  feat->fp16  ||  W->fp16 ------------
__global__ void __launch_bounds__(256)
mega_kernel(const int* __restrict__ erow, const int* __restrict__ ecol,
            const float* __restrict__ eval, const float* __restrict__ feat,
            const float* __restrict__ W) {
    int b = blockIdx.x;
    int tid = threadIdx.x;
    if (b < FILL_BLOCKS) {
        int e = b * 256 + tid;
        if (e < N_EDGES) {
            int   r = erow[e];
            float v = eval[e];
            unsigned long long q =
                (1ull << 42) + (unsigned long long)(v * 16777216.0f);
            unsigned long long old = atomicAdd(&g_pack[r], q);
            int slot = (int)(old >> 42);
            g_ell[(size_t)r * ELLW + slot] = make_int2(ecol[e], __float_as_int(v));
        }
    } else if (b < FILL_BLOCKS + CONV_BLOCKS) {
        int idx = (b - FILL_BLOCKS) * 256 + tid;     // float4 index, exact fit
        float4 f = __ldg(((const float4*)feat) + idx);
        union { __half2 h[2]; uint2 u; } u;
        u.h[0] = __floats2half2_rn(f.x, f.y);
        u.h[1] = __floats2half2_rn(f.z, f.w);
        ((uint2*)g_feath)[idx] = u.u;
    } else {
        int k = b - FILL_BLOCKS - CONV_BLOCKS;       // 0..127
        int n = tid;                                  // 0..255
        g_Wh[(size_t)n * D_FEAT + k] = __float2half_rn(W[(size_t)k * UNITS + n]);
    }
}

// -------------------------------------------------------------- invd --------
__global__ void invd_kernel() {
    int i = blockIdx.x * blockDim.x + threadIdx.x;
    if (i < N_NODES) g_invd[i] = pack_to_inv(g_pack[i]);
}

// ---------------------- gather SpMM (fp16 A out) ----------------------------
// One warp per row; Round-8 loop shape (low regs, high occ). Edge weight
// premultiplied with invd[col] during the cooperative metadata load.
__global__ void __launch_bounds__(256)
gather_kernel(const float* __restrict__ feat) {
    int warp = (blockIdx.x * blockDim.x + threadIdx.x) >> 5;
    int lane = threadIdx.x & 31;
    if (warp >= N_NODES) return;
    const int r = warp;

    unsigned long long p = g_pack[r];
    const int deg = (int)(p >> 42);
    float inv  = pack_to_inv(p);
    float inv2 = inv * inv;
    float4 sf = __ldg((const float4*)(feat + (size_t)r * D_FEAT) + lane);
    float4 acc = make_float4(inv2 * sf.x, inv2 * sf.y, inv2 * sf.z, inv2 * sf.w);

    const int2* ebase = g_ell + (size_t)r * ELLW;

    int done = 0;
    while (done < deg) {
        const int chunk = min(32, deg - done);
        // cooperative metadata load + invd premultiply
        // (lanes >= chunk: col 0, weight 0 -> cached dummy gather, adds 0)
        int   c_my = 0;
        float w_my = 0.0f;
        if (lane < chunk) {
            int2 ev = __ldg(ebase + done + lane);
            c_my = ev.x;
            w_my = __int_as_float(ev.y) * __ldg(&g_invd[ev.x]);
        }
        const int nb8 = (chunk + 7) & ~7;   // dummy edges are free

        for (int d = 0; d < nb8; d += 8) {
            int   cs[8];
            float ws[8];
            #pragma unroll
            for (int j = 0; j < 8; j++) {
                cs[j] = __shfl_sync(0xffffffffu, c_my, d + j);
                ws[j] = __shfl_sync(0xffffffffu, w_my, d + j);
            }
            uint2 ms[8];
            #pragma unroll
            for (int j = 0; j < 8; j++)
                ms[j] = __ldg((const uint2*)(g_feath + (size_t)cs[j] * D_FEAT) + lane);
            #pragma unroll
            for (int j = 0; j < 8; j++) {
                union { uint2 u; __half2 h[2]; } m; m.u = ms[j];
                float2 f01 = __half22float2(m.h[0]);
                float2 f23 = __half22float2(m.h[1]);
                acc.x = fmaf(ws[j], f01.x, acc.x);
                acc.y = fmaf(ws[j], f01.y, acc.y);
                acc.z = fmaf(ws[j], f23.x, acc.z);
                acc.w = fmaf(ws[j], f23.y, acc.w);
            }
        }
        done += chunk;
    }

    // write fp16 A row directly
    union { __half2 h[2]; uint2 u; } o;
    o.h[0] = __floats2half2_rn(acc.x, acc.y);
    o.h[1] = __floats2half2_rn(acc.z, acc.w);
    *(uint2*)(g_Ah + (size_t)r * D_FEAT + lane * 4) = o.u;
}

// --------------------------------------------- mma.sync fp16 GEMM -----------
#define AS_STRIDE 136

__device__ __forceinline__ void ldmat_x4(uint32_t& r0, uint32_t& r1,
                                         uint32_t& r2, uint32_t& r3,
                                         uint32_t addr) {
    asm volatile("ldmatrix.sync.aligned.m8n8.x4.shared.b16 {%0,%1,%2,%3}, [%4];"
                 : "=r"(r0), "=r"(r1), "=r"(r2), "=r"(r3) : "r"(addr));
}

__global__ void __launch_bounds__(256)
gemm_mma_kernel(float* __restrict__ out) {
    extern __shared__ __half smem[];
    __half* As = smem;                        // [128][AS_STRIDE]
    __half* Bs = smem + 128 * AS_STRIDE;      // [128][AS_STRIDE], [n][k]

    uint32_t sbase;
    asm("{ .reg .u64 t; cvta.to.shared.u64 t, %1; cvt.u32.u64 %0, t; }"
        : "=r"(sbase) : "l"(smem));
    const uint32_t bs_base = sbase + 128 * AS_STRIDE * 2;

    const int tid  = threadIdx.x;
    const int wid  = tid >> 5;
    const int lane = tid & 31;
    const int g    = lane >> 2;
    const int tg   = lane & 3;
    const int wm   = (wid & 3) * 32;
    const int wn   = (wid >> 2) * 64;
    const int bm   = blockIdx.x * 128;
    const int bn   = blockIdx.y * 128;

    uint32_t aoff[2];
    #pragma unroll
    for (int i = 0; i < 2; i++)
        aoff[i] = sbase +
            (uint32_t)(((wm + i * 16 + (lane & 15)) * AS_STRIDE +
                        (lane >> 4) * 8) * 2);
    uint32_t boff[4];
    #pragma unroll
    for (int jp = 0; jp < 4; jp++)
        boff[jp] = bs_base +
            (uint32_t)(((wn + jp * 16 + ((lane >> 4) * 8) + (lane & 7)) * AS_STRIDE +
                        ((lane >> 3) & 1) * 8) * 2);

    float acc[2][8][4];
    #pragma unroll
    for (int i = 0; i < 2; i++)
        #pragma unroll
        for (int j = 0; j < 8; j++)
            #pragma unroll
            for (int q = 0; q < 4; q++) acc[i][j][q] = 0.0f;

    {
        const uint4* Ag = (const uint4*)(g_Ah + (size_t)bm * D_FEAT);
        const uint4* Bg = (const uint4*)(g_Wh + (size_t)bn * D_FEAT);
        #pragma unroll
        for (int i = tid; i < 2048; i += 256) {
            int r = i >> 4, c = i & 15;
            *(uint4*)(As + r * AS_STRIDE + c * 8) = __ldg(Ag + i);
        }
        #pragma unroll
        for (int i = tid; i < 2048; i += 256) {
            int r = i >> 4, c = i & 15;
            *(uint4*)(Bs + r * AS_STRIDE + c * 8) = __ldg(Bg + i);
        }
    }
    __syncthreads();

    #pragma unroll
    for (int kk = 0; kk < D_FEAT; kk += 16) {
        uint32_t a[2][4];
        #pragma unroll
        for (int i = 0; i < 2; i++)
            ldmat_x4(a[i][0], a[i][1], a[i][2], a[i][3], aoff[i] + kk * 2);
        uint32_t b[8][2];
        #pragma unroll
        for (int jp = 0; jp < 4; jp++)
            ldmat_x4(b[jp * 2][0], b[jp * 2][1],
                     b[jp * 2 + 1][0], b[jp * 2 + 1][1],
                     boff[jp] + kk * 2);
        #pragma unroll
        for (int i = 0; i < 2; i++)
            #pragma unroll
            for (int j = 0; j < 8; j++) {
                asm volatile(
                    "mma.sync.aligned.m16n8k16.row.col.f32.f16.f16.f32 "
                    "{%0,%1,%2,%3}, {%4,%5,%6,%7}, {%8,%9}, {%0,%1,%2,%3};"
                    : "+f"(acc[i][j][0]), "+f"(acc[i][j][1]),
                      "+f"(acc[i][j][2]), "+f"(acc[i][j][3])
                    : "r"(a[i][0]), "r"(a[i][1]), "r"(a[i][2]), "r"(a[i][3]),
                      "r"(b[j][0]), "r"(b[j][1]));
            }
    }

    #pragma unroll
    for (int i = 0; i < 2; i++) {
        int row0 = bm + wm + i * 16 + g;
        int row1 = row0 + 8;
        #pragma unroll
        for (int j = 0; j < 8; j++) {
            int col = bn + wn + j * 8 + tg * 2;
            if (row0 < N_NODES) {
                float2 o0 = make_float2(fmaxf(acc[i][j][0], 0.0f),
                                        fmaxf(acc[i][j][1], 0.0f));
                *(float2*)&out[(size_t)row0 * UNITS + col] = o0;
            }
            if (row1 < N_NODES) {
                float2 o1 = make_float2(fmaxf(acc[i][j][2], 0.0f),
                                        fmaxf(acc[i][j][3], 0.0f));
                *(float2*)&out[(size_t)row1 * UNITS + col] = o1;
            }
        }
    }
}

#define GEMM_SMEM_BYTES (2 * 128 * AS_STRIDE * 2)   // 69632

// ------------------------------------------------------------------ launch --
extern "C" void kernel_launch(void* const* d_in, const int* in_sizes, int n_in,
                              void* d_out, int out_size) {
    const float* features = (const float*)d_in[0];
    const int*   edge_row = (const int*)d_in[1];
    const int*   edge_col = (const int*)d_in[2];
    const float* edge_val = (const float*)d_in[3];
    const float* W        = (const float*)d_in[4];
    float*       out      = (float*)d_out;

    zero_kernel<<<(N_NODES + 255) / 256, 256>>>();
    mega_kernel<<<MEGA_BLOCKS, 256>>>(edge_row, edge_col, edge_val,
                                      features, W);
    invd_kernel<<<(N_NODES + 255) / 256, 256>>>();
    gather_kernel<<<(N_NODES * 32 + 255) / 256, 256>>>(features);

    static bool smem_set = false;
    if (!smem_set) {
        cudaFuncSetAttribute(gemm_mma_kernel,
                             cudaFuncAttributeMaxDynamicSharedMemorySize,
                             GEMM_SMEM_BYTES);
        smem_set = true;
    }
    dim3 grid(N_PAD / 128, UNITS / 128);
    gemm_mma_kernel<<<grid, 256, GEMM_SMEM_BYTES>>>(out);
}

// round 11
// speedup vs baseline: 1.3951x; 1.3951x over previous
#include <cuda_runtime.h>
#include <cuda_fp16.h>
#include <cstdint>

#define N_NODES 50000
#define N_PAD   50048      // 391 * 128
#define N_EDGES 800000
#define D_FEAT  128
#define UNITS   256
#define ELLW    80         // padded ELL width (max degree ~35 whp)

#define FILL_BLOCKS 3125   // N_EDGES / 256
#define CW_BLOCKS   128    // D_FEAT
#define PRE_BLOCKS  (FILL_BLOCKS + CW_BLOCKS)

// ---------------------------------------------------------------- scratch ---
__device__ unsigned long long g_pack[N_NODES];  // count<<42 | fix24(val sum)
__device__ int2   g_ell[(size_t)N_NODES * ELLW];   // {col, val-bits}
__device__ __half g_normh[(size_t)N_NODES * D_FEAT];  // invd-scaled fp16 feats
// fp16 GEMM operands (zero-init; pad rows never written -> stay zero)
__device__ __half g_Ah[(size_t)N_PAD * D_FEAT];
__device__ __half g_Wh[(size_t)UNITS * D_FEAT];    // transposed: [n][k]

// -------------------------------------------------------------------- zero --
__global__ void zero_kernel() {
    int i = blockIdx.x * blockDim.x + threadIdx.x;
    if (i < N_NODES) g_pack[i] = 0ull;
}

__device__ __forceinline__ float pack_to_inv(unsigned long long p) {
    float deg = (float)(p & ((1ull << 42) - 1)) * (1.0f / 16777216.0f);
    return rsqrtf(deg + 1.0f);
}

// ----------------------- pre: ELL fill  ||  W->fp16 -------------------------
__global__ void __launch_bounds__(256)
pre_kernel(const int* __restrict__ erow, const int* __restrict__ ecol,
           const float* __restrict__ eval, const float* __restrict__ W) {
    int b = blockIdx.x;
    int tid = threadIdx.x;
    if (b < FILL_BLOCKS) {
        int e = b * 256 + tid;
        if (e < N_EDGES) {
            int   r = erow[e];
            float v = eval[e];
            unsigned long long q =
                (1ull << 42) + (unsigned long long)(v * 16777216.0f);
            unsigned long long old = atomicAdd(&g_pack[r], q);
            int slot = (int)(old >> 42);
            g_ell[(size_t)r * ELLW + slot] = make_int2(ecol[e], __float_as_int(v));
        }
    } else {
        int k = b - FILL_BLOCKS;   // 0..127
        int n = tid;               // 0..255
        g_Wh[(size_t)n * D_FEAT + k] = __float2half_rn(W[(size_t)k * UNITS + n]);
    }
}

// ---------------------------------------------- normalize -> fp16 -----------
__global__ void normalize_kernel(const float* __restrict__ feat) {
    int idx = blockIdx.x * blockDim.x + threadIdx.x;   // 4-elem index
    const int total = N_NODES * (D_FEAT / 4);
    if (idx >= total) return;
    int n = idx >> 5;
    float inv = pack_to_inv(g_pack[n]);
    float4 f = __ldg(((const float4*)feat) + idx);
    union { __half2 h[2]; uint2 u; } u;
    u.h[0] = __floats2half2_rn(f.x * inv, f.y * inv);
    u.h[1] = __floats2half2_rn(f.z * inv, f.w * inv);
    ((uint2*)g_normh)[idx] = u.u;
}

// ---------------------- gather SpMM (fp16 A out) ----------------------------
// One warp per row, HALF-WARP PAIRED gathers: each half-warp loads a full
// 256B row with 16 x LDG.128 (8 halves per lane) -> 2 edges per batch slot,
// half the gather instructions of the 64-bit scheme. Accumulators are
// combined across half-warps once at the end (shfl_xor 16).
__global__ void __launch_bounds__(256)
gather_kernel(const float* __restrict__ feat) {
    int warp = (blockIdx.x * blockDim.x + threadIdx.x) >> 5;
    int lane = threadIdx.x & 31;
    if (warp >= N_NODES) return;
    const int r = warp;
    const int h = lane >> 4;       // half-warp id
    const int s = lane & 15;       // sublane: features [8s .. 8s+7]

    unsigned long long p = g_pack[r];
    const int deg = (int)(p >> 42);
    float inv  = pack_to_inv(p);
    float inv2 = inv * inv;

    float acc[8];
    #pragma unroll
    for (int q = 0; q < 8; q++) acc[q] = 0.0f;

    const int2* ebase = g_ell + (size_t)r * ELLW;

    int done = 0;
    while (done < deg) {
        const int chunk = min(32, deg - done);
        // cooperative metadata load (lanes >= chunk: col 0, weight 0 dummy)
        int   c_my = 0;
        float w_my = 0.0f;
        if (lane < chunk) {
            int2 ev = __ldg(ebase + done + lane);
            c_my = ev.x;
            w_my = __int_as_float(ev.y);
        }
        const int nb8 = (chunk + 7) & ~7;   // dummy edges are free

        for (int d = 0; d < nb8; d += 8) {
            // half-warp 0 takes edges d..d+3, half-warp 1 takes d+4..d+7
            int   cs[4];
            float ws[4];
            #pragma unroll
            for (int j = 0; j < 4; j++) {
                cs[j] = __shfl_sync(0xffffffffu, c_my, d + h * 4 + j);
                ws[j] = __shfl_sync(0xffffffffu, w_my, d + h * 4 + j);
            }
            uint4 ms[4];
            #pragma unroll
            for (int j = 0; j < 4; j++)
                ms[j] = __ldg((const uint4*)(g_normh + (size_t)cs[j] * D_FEAT) + s);
            #pragma unroll
            for (int j = 0; j < 4; j++) {
                const __half2* hh = (const __half2*)&ms[j];
                #pragma unroll
                for (int q = 0; q < 4; q++) {
                    float2 f = __half22float2(hh[q]);
                    acc[2 * q]     = fmaf(ws[j], f.x, acc[2 * q]);
                    acc[2 * q + 1] = fmaf(ws[j], f.y, acc[2 * q + 1]);
                }
            }
        }
        done += chunk;
    }

    // combine the two half-warp partial sums
    #pragma unroll
    for (int q = 0; q < 8; q++)
        acc[q] += __shfl_xor_sync(0xffffffffu, acc[q], 16);

    if (h == 0) {
        // self-loop term in fp32, then store 8 halves (one uint4)
        float4 f0 = __ldg((const float4*)(feat + (size_t)r * D_FEAT) + 2 * s);
        float4 f1 = __ldg((const float4*)(feat + (size_t)r * D_FEAT) + 2 * s + 1);
        acc[0] = fmaf(inv2, f0.x, acc[0]);
        acc[1] = fmaf(inv2, f0.y, acc[1]);
        acc[2] = fmaf(inv2, f0.z, acc[2]);
        acc[3] = fmaf(inv2, f0.w, acc[3]);
        acc[4] = fmaf(inv2, f1.x, acc[4]);
        acc[5] = fmaf(inv2, f1.y, acc[5]);
        acc[6] = fmaf(inv2, f1.z, acc[6]);
        acc[7] = fmaf(inv2, f1.w, acc[7]);
        union { __half2 hh[4]; uint4 u; } o;
        o.hh[0] = __floats2half2_rn(acc[0], acc[1]);
        o.hh[1] = __floats2half2_rn(acc[2], acc[3]);
        o.hh[2] = __floats2half2_rn(acc[4], acc[5]);
        o.hh[3] = __floats2half2_rn(acc[6], acc[7]);
        *(uint4*)(g_Ah + (size_t)r * D_FEAT + s * 8) = o.u;
    }
}

// --------------------------------------------- mma.sync fp16 GEMM -----------
#define AS_STRIDE 136

__device__ __forceinline__ void ldmat_x4(uint32_t& r0, uint32_t& r1,
                                         uint32_t& r2, uint32_t& r3,
                                         uint32_t addr) {
    asm volatile("ldmatrix.sync.aligned.m8n8.x4.shared.b16 {%0,%1,%2,%3}, [%4];"
                 : "=r"(r0), "=r"(r1), "=r"(r2), "=r"(r3) : "r"(addr));
}

__global__ void __launch_bounds__(256)
gemm_mma_kernel(float* __restrict__ out) {
    extern __shared__ __half smem[];
    __half* As = smem;                        // [128][AS_STRIDE]
    __half* Bs = smem + 128 * AS_STRIDE;      // [128][AS_STRIDE], [n][k]

    uint32_t sbase;
    asm("{ .reg .u64 t; cvta.to.shared.u64 t, %1; cvt.u32.u64 %0, t; }"
        : "=r"(sbase) : "l"(smem));
    const uint32_t bs_base = sbase + 128 * AS_STRIDE * 2;

    const int tid  = threadIdx.x;
    const int wid  = tid >> 5;
    const int lane = tid & 31;
    const int g    = lane >> 2;
    const int tg   = lane & 3;
    const int wm   = (wid & 3) * 32;
    const int wn   = (wid >> 2) * 64;
    const int bm   = blockIdx.x * 128;
    const int bn   = blockIdx.y * 128;

    uint32_t aoff[2];
    #pragma unroll
    for (int i = 0; i < 2; i++)
        aoff[i] = sbase +
            (uint32_t)(((wm + i * 16 + (lane & 15)) * AS_STRIDE +
                        (lane >> 4) * 8) * 2);
    uint32_t boff[4];
    #pragma unroll
    for (int jp = 0; jp < 4; jp++)
        boff[jp] = bs_base +
            (uint32_t)(((wn + jp * 16 + ((lane >> 4) * 8) + (lane & 7)) * AS_STRIDE +
                        ((lane >> 3) & 1) * 8) * 2);

    float acc[2][8][4];
    #pragma unroll
    for (int i = 0; i < 2; i++)
        #pragma unroll
        for (int j = 0; j < 8; j++)
            #pragma unroll
            for (int q = 0; q < 4; q++) acc[i][j][q] = 0.0f;

    {
        const uint4* Ag = (const uint4*)(g_Ah + (size_t)bm * D_FEAT);
        const uint4* Bg = (const uint4*)(g_Wh + (size_t)bn * D_FEAT);
        #pragma unroll
        for (int i = tid; i < 2048; i += 256) {
            int r = i >> 4, c = i & 15;
            *(uint4*)(As + r * AS_STRIDE + c * 8) = __ldg(Ag + i);
        }
        #pragma unroll
        for (int i = tid; i < 2048; i += 256) {
            int r = i >> 4, c = i & 15;
            *(uint4*)(Bs + r * AS_STRIDE + c * 8) = __ldg(Bg + i);
        }
    }
    __syncthreads();

    #pragma unroll
    for (int kk = 0; kk < D_FEAT; kk += 16) {
        uint32_t a[2][4];
        #pragma unroll
        for (int i = 0; i < 2; i++)
            ldmat_x4(a[i][0], a[i][1], a[i][2], a[i][3], aoff[i] + kk * 2);
        uint32_t b[8][2];
        #pragma unroll
        for (int jp = 0; jp < 4; jp++)
            ldmat_x4(b[jp * 2][0], b[jp * 2][1],
                     b[jp * 2 + 1][0], b[jp * 2 + 1][1],
                     boff[jp] + kk * 2);
        #pragma unroll
        for (int i = 0; i < 2; i++)
            #pragma unroll
            for (int j = 0; j < 8; j++) {
                asm volatile(
                    "mma.sync.aligned.m16n8k16.row.col.f32.f16.f16.f32 "
                    "{%0,%1,%2,%3}, {%4,%5,%6,%7}, {%8,%9}, {%0,%1,%2,%3};"
                    : "+f"(acc[i][j][0]), "+f"(acc[i][j][1]),
                      "+f"(acc[i][j][2]), "+f"(acc[i][j][3])
                    : "r"(a[i][0]), "r"(a[i][1]), "r"(a[i][2]), "r"(a[i][3]),
                      "r"(b[j][0]), "r"(b[j][1]));
            }
    }

    #pragma unroll
    for (int i = 0; i < 2; i++) {
        int row0 = bm + wm + i * 16 + g;
        int row1 = row0 + 8;
        #pragma unroll
        for (int j = 0; j < 8; j++) {
            int col = bn + wn + j * 8 + tg * 2;
            if (row0 < N_NODES) {
                float2 o0 = make_float2(fmaxf(acc[i][j][0], 0.0f),
                                        fmaxf(acc[i][j][1], 0.0f));
                *(float2*)&out[(size_t)row0 * UNITS + col] = o0;
            }
            if (row1 < N_NODES) {
                float2 o1 = make_float2(fmaxf(acc[i][j][2], 0.0f),
                                        fmaxf(acc[i][j][3], 0.0f));
                *(float2*)&out[(size_t)row1 * UNITS + col] = o1;
            }
        }
    }
}

#define GEMM_SMEM_BYTES (2 * 128 * AS_STRIDE * 2)   // 69632

// ------------------------------------------------------------------ launch --
extern "C" void kernel_launch(void* const* d_in, const int* in_sizes, int n_in,
                              void* d_out, int out_size) {
    const float* features = (const float*)d_in[0];
    const int*   edge_row = (const int*)d_in[1];
    const int*   edge_col = (const int*)d_in[2];
    const float* edge_val = (const float*)d_in[3];
    const float* W        = (const float*)d_in[4];
    float*       out      = (float*)d_out;

    zero_kernel<<<(N_NODES + 255) / 256, 256>>>();
    pre_kernel<<<PRE_BLOCKS, 256>>>(edge_row, edge_col, edge_val, W);

    const int nf4 = N_NODES * (D_FEAT / 4);
    normalize_kernel<<<(nf4 + 255) / 256, 256>>>(features);

    gather_kernel<<<(N_NODES * 32 + 255) / 256, 256>>>(features);

    static bool smem_set = false;
    if (!smem_set) {
        cudaFuncSetAttribute(gemm_mma_kernel,
                             cudaFuncAttributeMaxDynamicSharedMemorySize,
                             GEMM_SMEM_BYTES);
        smem_set = true;
    }
    dim3 grid(N_PAD / 128, UNITS / 128);
    gemm_mma_kernel<<<grid, 256, GEMM_SMEM_BYTES>>>(out);
}